// round 3
// baseline (speedup 1.0000x reference)
#include <cuda_runtime.h>
#include <math.h>

#define NN 8192
#define DD 256
#define TK 5
#define TOPC 8   // candidates kept per row before exact A-level selection

// ---------------- device scratch (no allocations allowed) ----------------
__device__ float g_psum[32][DD];
__device__ float g_psq[32][DD];
__device__ float g_scale[DD];
__device__ float g_shift[DD];
__device__ float g_HnT[DD * NN];   // transposed normalized input [k][row]
__device__ float g_Hx[NN * DD];    // theta projection (row-major, pre-normalize)
__device__ float g_F1T[DD * NN];   // normalized F1, transposed [k][row]
__device__ float g_G[NN * DD];     // Hn @ W_out + b_out (row-major)
__device__ float g_tv[NN * TK];    // top-5 A values per row
__device__ int   g_ti[NN * TK];    // top-5 indices per row
__device__ float g_dinv[NN];
__device__ float g_S[(size_t)NN * NN];  // full similarity matrix (268 MB)

// ---------------- 1) batchnorm stats: partial sums ----------------
__global__ void k_stats1(const float* __restrict__ H) {
    int b = blockIdx.x, t = threadIdx.x;
    const float* p = H + (size_t)b * 256 * DD + t;
    float s = 0.f, q = 0.f;
#pragma unroll 8
    for (int r = 0; r < 256; r++) {
        float x = p[(size_t)r * DD];
        s += x; q += x * x;
    }
    g_psum[b][t] = s;
    g_psq[b][t]  = q;
}

// ---------------- 2) finalize stats ----------------
__global__ void k_stats2(const float* __restrict__ gamma, const float* __restrict__ beta) {
    int t = threadIdx.x;
    float s = 0.f, q = 0.f;
    for (int b = 0; b < 32; b++) { s += g_psum[b][t]; q += g_psq[b][t]; }
    float mu  = s * (1.f / NN);
    float var = q * (1.f / NN) - mu * mu;
    float sc  = gamma[t] * rsqrtf(var + 1e-5f);
    g_scale[t] = sc;
    g_shift[t] = beta[t] - mu * sc;
}

// ---------------- 3) Hn (normalized), written TRANSPOSED [k][row] ----------------
__global__ void k_hnT(const float* __restrict__ H) {
    __shared__ float buf[32 * 257];
    int r0 = blockIdx.x * 32;
    int tid = threadIdx.x;
#pragma unroll
    for (int it = 0; it < 8; it++) {
        int e = it * 256 + tid;
        int r = e >> 6;
        int c = (e & 63) * 4;
        float4 h = *(const float4*)(H + (size_t)(r0 + r) * DD + c);
        buf[r * 257 + c + 0] = fmaf(h.x, g_scale[c + 0], g_shift[c + 0]);
        buf[r * 257 + c + 1] = fmaf(h.y, g_scale[c + 1], g_shift[c + 1]);
        buf[r * 257 + c + 2] = fmaf(h.z, g_scale[c + 2], g_shift[c + 2]);
        buf[r * 257 + c + 3] = fmaf(h.w, g_scale[c + 3], g_shift[c + 3]);
    }
    __syncthreads();
    int lane = tid & 31;
    int cbase = tid >> 5;
#pragma unroll
    for (int it = 0; it < 32; it++) {
        int c = cbase + it * 8;
        g_HnT[(size_t)c * NN + r0 + lane] = buf[lane * 257 + c];
    }
}

// ---------------- 4) GEMM: [Hx | G] = Hn @ [W_theta | W_out] + bias ----------------
__global__ __launch_bounds__(256) void k_gemm(
    const float* __restrict__ Wt, const float* __restrict__ bt,
    const float* __restrict__ Wo, const float* __restrict__ bo) {
    __shared__ float As[64 * 64];
    __shared__ float Bs[64 * 64];
    int tid = threadIdx.x, tx = tid & 15, ty = tid >> 4;
    int i0 = blockIdx.x * 64;
    int by = blockIdx.y;
    const float* W    = (by < 4) ? Wt : Wo;
    const float* bias = (by < 4) ? bt : bo;
    float* C          = (by < 4) ? g_Hx : g_G;
    int n0 = (by & 3) * 64;

    float acc[4][4] = {};
    for (int kc = 0; kc < 256; kc += 64) {
#pragma unroll
        for (int it = 0; it < 4; it++) {
            int e = it * 256 + tid;
            int k = e >> 4, r4 = e & 15;
            float4 v = *(const float4*)(g_HnT + (size_t)(kc + k) * NN + i0 + r4 * 4);
            *(float4*)(As + k * 64 + r4 * 4) = v;
        }
#pragma unroll
        for (int it = 0; it < 4; it++) {
            int e = it * 256 + tid;
            int k = e >> 4, n4 = e & 15;
            float4 v = *(const float4*)(W + (size_t)(kc + k) * DD + n0 + n4 * 4);
            *(float4*)(Bs + k * 64 + n4 * 4) = v;
        }
        __syncthreads();
#pragma unroll 8
        for (int k = 0; k < 64; k++) {
            float4 a = *(const float4*)(As + k * 64 + ty * 4);
            float4 b = *(const float4*)(Bs + k * 64 + tx * 4);
            acc[0][0] += a.x * b.x; acc[0][1] += a.x * b.y; acc[0][2] += a.x * b.z; acc[0][3] += a.x * b.w;
            acc[1][0] += a.y * b.x; acc[1][1] += a.y * b.y; acc[1][2] += a.y * b.z; acc[1][3] += a.y * b.w;
            acc[2][0] += a.z * b.x; acc[2][1] += a.z * b.y; acc[2][2] += a.z * b.z; acc[2][3] += a.z * b.w;
            acc[3][0] += a.w * b.x; acc[3][1] += a.w * b.y; acc[3][2] += a.w * b.z; acc[3][3] += a.w * b.w;
        }
        __syncthreads();
    }
#pragma unroll
    for (int q = 0; q < 4; q++) {
        int r = i0 + ty * 4 + q;
#pragma unroll
        for (int p = 0; p < 4; p++) {
            int n = n0 + tx * 4 + p;
            C[(size_t)r * DD + n] = acc[q][p] + bias[n];
        }
    }
}

// ---------------- 5) row-normalize Hx -> F1, written TRANSPOSED ----------------
__global__ void k_norm() {
    __shared__ float buf[32 * 257];
    int r0 = blockIdx.x * 32;
    int tid = threadIdx.x, w = tid >> 5, lane = tid & 31;
#pragma unroll
    for (int rr = w * 4; rr < w * 4 + 4; rr++) {
        const float* row = g_Hx + (size_t)(r0 + rr) * DD;
        float4 x0 = ((const float4*)row)[lane];
        float4 x1 = ((const float4*)row)[lane + 32];
        float s = x0.x * x0.x + x0.y * x0.y + x0.z * x0.z + x0.w * x0.w
                + x1.x * x1.x + x1.y * x1.y + x1.z * x1.z + x1.w * x1.w;
#pragma unroll
        for (int o = 16; o > 0; o >>= 1) s += __shfl_xor_sync(0xffffffffu, s, o);
        float inv = 1.f / fmaxf(sqrtf(s), 1e-12f);
        int c0 = lane * 4, c1 = 128 + lane * 4;
        buf[rr * 257 + c0 + 0] = x0.x * inv; buf[rr * 257 + c0 + 1] = x0.y * inv;
        buf[rr * 257 + c0 + 2] = x0.z * inv; buf[rr * 257 + c0 + 3] = x0.w * inv;
        buf[rr * 257 + c1 + 0] = x1.x * inv; buf[rr * 257 + c1 + 1] = x1.y * inv;
        buf[rr * 257 + c1 + 2] = x1.z * inv; buf[rr * 257 + c1 + 3] = x1.w * inv;
    }
    __syncthreads();
    int cbase = tid >> 5;
#pragma unroll
    for (int it = 0; it < 32; it++) {
        int c = cbase + it * 8;
        g_F1T[(size_t)c * NN + r0 + lane] = buf[lane * 257 + c];
    }
}

// map clipped cosine -> A value, matching the reference formula in fp32
__device__ __forceinline__ float affinity(float d) {
    d = fminf(fmaxf(d, -1.f), 1.f);
    float sam = acosf(d);
    float e = expf(-0.2f * sam);
    float a = 1.f / (1.f + expf(-e));
    return fmaxf(a, 0.1f);
}

__device__ __forceinline__ float lo32(unsigned long long x) { return __uint_as_float((unsigned)x); }
__device__ __forceinline__ float hi32(unsigned long long x) { return __uint_as_float((unsigned)(x >> 32)); }

// ---------------- 6) symmetric S tiles: 128x128 per CTA, f32x2 packed FMA ----------------
// Computes only upper-triangular tiles (it<=jt), stores both orientations.
__global__ __launch_bounds__(256) void k_sym() {
    extern __shared__ float sm[];
    float* Ai = sm;              // [64k][128r]
    float* Bd = sm + 64 * 128;   // [64k][256] duplicated pairs (b,b)

    int tid = threadIdx.x, tx = tid & 15, ty = tid >> 4;

    // decode upper-triangular tile index
    int t = blockIdx.x, it = 0, rem = t;
    while (rem >= 64 - it) { rem -= 64 - it; it++; }
    int jt = it + rem;
    int i0 = it * 128, j0 = jt * 128;

    // acc pairs packed along r: acc2[r2][c] = (S[2r2][c], S[2r2+1][c])
    unsigned long long acc2[4][8];
#pragma unroll
    for (int a = 0; a < 4; a++)
#pragma unroll
        for (int b = 0; b < 8; b++) acc2[a][b] = 0ull;

    for (int kc = 0; kc < 256; kc += 64) {
#pragma unroll
        for (int it2 = 0; it2 < 8; it2++) {
            int e = it2 * 256 + tid;
            int k = e >> 5, r4 = e & 31;
            const float* src = g_F1T + (size_t)(kc + k) * NN;
            float4 a = *(const float4*)(src + i0 + r4 * 4);
            *(float4*)(Ai + k * 128 + r4 * 4) = a;
            float4 b = *(const float4*)(src + j0 + r4 * 4);
            *(float4*)(Bd + k * 256 + r4 * 8)     = make_float4(b.x, b.x, b.y, b.y);
            *(float4*)(Bd + k * 256 + r4 * 8 + 4) = make_float4(b.z, b.z, b.w, b.w);
        }
        __syncthreads();
#pragma unroll 8
        for (int k = 0; k < 64; k++) {
            ulonglong2 a01 = *(const ulonglong2*)(Ai + k * 128 + ty * 8);
            ulonglong2 a23 = *(const ulonglong2*)(Ai + k * 128 + ty * 8 + 4);
            unsigned long long a2[4] = { a01.x, a01.y, a23.x, a23.y };
            const unsigned long long* bd = (const unsigned long long*)(Bd + k * 256 + tx * 16);
#pragma unroll
            for (int c = 0; c < 8; c++) {
                unsigned long long bb = bd[c];
#pragma unroll
                for (int r2 = 0; r2 < 4; r2++) {
                    asm("fma.rn.f32x2 %0, %1, %2, %0;"
                        : "+l"(acc2[r2][c]) : "l"(a2[r2]), "l"(bb));
                }
            }
        }
        __syncthreads();
    }

    // direct store: rows i0+ty*8+r, cols j0+tx*8..
#pragma unroll
    for (int r = 0; r < 8; r++) {
        int r2 = r >> 1;
        float4 v0, v1;
        if (r & 1) {
            v0 = make_float4(hi32(acc2[r2][0]), hi32(acc2[r2][1]), hi32(acc2[r2][2]), hi32(acc2[r2][3]));
            v1 = make_float4(hi32(acc2[r2][4]), hi32(acc2[r2][5]), hi32(acc2[r2][6]), hi32(acc2[r2][7]));
        } else {
            v0 = make_float4(lo32(acc2[r2][0]), lo32(acc2[r2][1]), lo32(acc2[r2][2]), lo32(acc2[r2][3]));
            v1 = make_float4(lo32(acc2[r2][4]), lo32(acc2[r2][5]), lo32(acc2[r2][6]), lo32(acc2[r2][7]));
        }
        float* dst = g_S + (size_t)(i0 + ty * 8 + r) * NN + j0 + tx * 8;
        *(float4*)dst = v0;
        *(float4*)(dst + 4) = v1;
    }
    // transposed store (skip on diagonal tiles)
    if (it != jt) {
#pragma unroll
        for (int c = 0; c < 8; c++) {
            float4 v0 = make_float4(lo32(acc2[0][c]), hi32(acc2[0][c]), lo32(acc2[1][c]), hi32(acc2[1][c]));
            float4 v1 = make_float4(lo32(acc2[2][c]), hi32(acc2[2][c]), lo32(acc2[3][c]), hi32(acc2[3][c]));
            float* dst = g_S + (size_t)(j0 + tx * 8 + c) * NN + i0 + ty * 8;
            *(float4*)dst = v0;
            *(float4*)(dst + 4) = v1;
        }
    }
}

// ---------------- 7) scan: per-row top-8 by (dot desc, idx asc), then A-level sort ----------------
__global__ __launch_bounds__(256) void k_topk() {
    __shared__ float sv[8][256];
    __shared__ int   sj[8][256];
    int w = threadIdx.x >> 5, lane = threadIdx.x & 31;
    int row = blockIdx.x * 8 + w;

    const float4* p = (const float4*)(g_S + (size_t)row * NN);
    float dv[TOPC]; int dj[TOPC];
#pragma unroll
    for (int m = 0; m < TOPC; m++) { dv[m] = -3.f; dj[m] = 0x7fffffff; }

#pragma unroll 4
    for (int t = 0; t < NN / 128; t++) {
        float4 v = p[t * 32 + lane];
        int j = (t * 32 + lane) * 4;
#pragma unroll
        for (int q = 0; q < 4; q++) {
            float vv = (q == 0) ? v.x : (q == 1) ? v.y : (q == 2) ? v.z : v.w;
            int jj = j + q;
            if (vv > dv[TOPC - 1] || (vv == dv[TOPC - 1] && jj < dj[TOPC - 1])) {
                dv[TOPC - 1] = vv; dj[TOPC - 1] = jj;
#pragma unroll
                for (int m = TOPC - 1; m > 0; m--) {
                    bool sw = dv[m] > dv[m - 1] || (dv[m] == dv[m - 1] && dj[m] < dj[m - 1]);
                    if (sw) {
                        float tf = dv[m]; dv[m] = dv[m - 1]; dv[m - 1] = tf;
                        int ti = dj[m]; dj[m] = dj[m - 1]; dj[m - 1] = ti;
                    }
                }
            }
        }
    }

#pragma unroll
    for (int m = 0; m < TOPC; m++) { sv[w][lane * TOPC + m] = dv[m]; sj[w][lane * TOPC + m] = dj[m]; }
    __syncwarp();

    if (lane == 0) {
        // merge other 31 lanes' candidates
        for (int l = 1; l < 32; l++) {
#pragma unroll
            for (int m = 0; m < TOPC; m++) {
                float vv = sv[w][l * TOPC + m];
                int jj = sj[w][l * TOPC + m];
                if (vv > dv[TOPC - 1] || (vv == dv[TOPC - 1] && jj < dj[TOPC - 1])) {
                    dv[TOPC - 1] = vv; dj[TOPC - 1] = jj;
#pragma unroll
                    for (int m2 = TOPC - 1; m2 > 0; m2--) {
                        bool sw = dv[m2] > dv[m2 - 1] || (dv[m2] == dv[m2 - 1] && dj[m2] < dj[m2 - 1]);
                        if (sw) {
                            float tf = dv[m2]; dv[m2] = dv[m2 - 1]; dv[m2 - 1] = tf;
                            int ti = dj[m2]; dj[m2] = dj[m2 - 1]; dj[m2 - 1] = ti;
                        }
                    }
                }
            }
        }

        // exact A values + stable sort by (A desc, idx asc) — matches lax.top_k ties
        float av[TOPC];
#pragma unroll
        for (int m = 0; m < TOPC; m++) av[m] = affinity(dv[m]);
#pragma unroll
        for (int m = 1; m < TOPC; m++) {
#pragma unroll
            for (int q = TOPC - 1; q >= 1; q--) {
                bool sw = (av[q] > av[q - 1]) ||
                          (av[q] == av[q - 1] && dj[q] < dj[q - 1]);
                if (sw) {
                    float tf = av[q]; av[q] = av[q - 1]; av[q - 1] = tf;
                    int ti = dj[q]; dj[q] = dj[q - 1]; dj[q - 1] = ti;
                }
            }
        }

        float rs = 0.f;
#pragma unroll
        for (int q = 0; q < TK; q++) {
            rs += av[q];
            g_tv[row * TK + q] = av[q];
            g_ti[row * TK + q] = dj[q];
        }
        g_dinv[row] = rsqrtf(rs);
    }
}

// ---------------- 8) scatter sparse A into dense output (if requested) ----------------
__global__ void k_scatterA(float* __restrict__ A) {
    int e = blockIdx.x * blockDim.x + threadIdx.x;
    if (e < NN * TK) {
        int row = e / TK;
        A[(size_t)row * NN + g_ti[e]] = g_tv[e];
    }
}

// ---------------- 9) out = leaky(A_hat @ G) via 5-neighbor gather ----------------
__global__ void k_out(float* __restrict__ out) {
    int i = blockIdx.x;
    int c4 = threadIdx.x;
    float di = g_dinv[i];
    float4 acc = make_float4(0.f, 0.f, 0.f, 0.f);
#pragma unroll
    for (int q = 0; q < TK; q++) {
        int j = g_ti[i * TK + q];
        float w = di * g_tv[i * TK + q] * g_dinv[j];
        float4 g = ((const float4*)(g_G + (size_t)j * DD))[c4];
        acc.x += w * g.x; acc.y += w * g.y; acc.z += w * g.z; acc.w += w * g.w;
    }
    acc.x = acc.x >= 0.f ? acc.x : 0.01f * acc.x;
    acc.y = acc.y >= 0.f ? acc.y : 0.01f * acc.y;
    acc.z = acc.z >= 0.f ? acc.z : 0.01f * acc.z;
    acc.w = acc.w >= 0.f ? acc.w : 0.01f * acc.w;
    ((float4*)(out + (size_t)i * DD))[c4] = acc;
}

// ---------------- launcher ----------------
extern "C" void kernel_launch(void* const* d_in, const int* in_sizes, int n_in,
                              void* d_out, int out_size) {
    const float* H     = (const float*)d_in[0];
    const float* gamma = (const float*)d_in[1];
    const float* beta  = (const float*)d_in[2];
    const float* Wt    = (const float*)d_in[3];
    const float* bt    = (const float*)d_in[4];
    const float* Wo    = (const float*)d_in[5];
    const float* bo    = (const float*)d_in[6];

    float* outbuf = (float*)d_out;
    const long long OUT_ND = (long long)NN * DD;
    const long long A_NN   = (long long)NN * NN;

    float* outp = nullptr;
    float* Ap   = nullptr;
    long long osz = (long long)out_size;
    if (osz == OUT_ND + A_NN)      { outp = outbuf; Ap = outbuf + OUT_ND; }
    else if (osz == A_NN)          { Ap = outbuf; }
    else if (osz == OUT_ND)        { outp = outbuf; }
    else                           { outp = outbuf; if (osz >= OUT_ND + A_NN) Ap = outbuf + OUT_ND; }

    size_t sym_smem = (size_t)(64 * 128 + 64 * 256) * sizeof(float);  // 96 KB
    cudaFuncSetAttribute(k_sym, cudaFuncAttributeMaxDynamicSharedMemorySize, (int)sym_smem);

    k_stats1<<<32, 256>>>(H);
    k_stats2<<<1, 256>>>(gamma, beta);
    k_hnT<<<NN / 32, 256>>>(H);
    {
        dim3 g(NN / 64, 8);
        k_gemm<<<g, 256>>>(Wt, bt, Wo, bo);
    }
    k_norm<<<NN / 32, 256>>>();

    k_sym<<<64 * 65 / 2, 256, sym_smem>>>();
    k_topk<<<NN / 8, 256>>>();

    if (Ap) {
        cudaMemsetAsync(Ap, 0, (size_t)A_NN * sizeof(float), 0);
        k_scatterA<<<(NN * TK + 255) / 256, 256>>>(Ap);
    }
    if (outp) {
        k_out<<<NN, 64>>>(outp);
    }
}

// round 4
// speedup vs baseline: 1.7420x; 1.7420x over previous
#include <cuda_runtime.h>
#include <math.h>

#define NN 8192
#define DD 256
#define TK 5
#define TOPC 8

#define RT 64      // rows per CTA in main kernel
#define JT 128     // j tile
#define KC 64      // k chunk for Fj
#define FI_PAD 260 // 260 mod 32 == 4 -> conflict-free frag loads
#define FJ_PAD 68  // 68 mod 32 == 4
#define S_PAD 132

// ---------------- device scratch ----------------
__device__ float g_psum[32][DD];
__device__ float g_psq[32][DD];
__device__ float g_scale[DD];
__device__ float g_shift[DD];
__device__ float g_HnT[DD * NN];    // transposed normalized input [k][row]
__device__ float g_Hx[NN * DD];     // theta projection (row-major)
__device__ float g_F1R[NN * DD];    // normalized F1, row-major (exact fp32)
__device__ float g_F1tf[NN * DD];   // tf32-rounded F1, row-major (mma operands)
__device__ float g_G[NN * DD];      // Hn @ W_out + b_out
__device__ float g_tv[NN * TK];
__device__ int   g_ti[NN * TK];
__device__ float g_dinv[NN];

// ---------------- 1) batchnorm stats ----------------
__global__ void k_stats1(const float* __restrict__ H) {
    int b = blockIdx.x, t = threadIdx.x;
    const float* p = H + (size_t)b * 256 * DD + t;
    float s = 0.f, q = 0.f;
#pragma unroll 8
    for (int r = 0; r < 256; r++) {
        float x = p[(size_t)r * DD];
        s += x; q += x * x;
    }
    g_psum[b][t] = s;
    g_psq[b][t]  = q;
}

__global__ void k_stats2(const float* __restrict__ gamma, const float* __restrict__ beta) {
    int t = threadIdx.x;
    float s = 0.f, q = 0.f;
    for (int b = 0; b < 32; b++) { s += g_psum[b][t]; q += g_psq[b][t]; }
    float mu  = s * (1.f / NN);
    float var = q * (1.f / NN) - mu * mu;
    float sc  = gamma[t] * rsqrtf(var + 1e-5f);
    g_scale[t] = sc;
    g_shift[t] = beta[t] - mu * sc;
}

// ---------------- 3) Hn transposed [k][row] (feeds k_gemm) ----------------
__global__ void k_hnT(const float* __restrict__ H) {
    __shared__ float buf[32 * 257];
    int r0 = blockIdx.x * 32;
    int tid = threadIdx.x;
#pragma unroll
    for (int it = 0; it < 8; it++) {
        int e = it * 256 + tid;
        int r = e >> 6;
        int c = (e & 63) * 4;
        float4 h = *(const float4*)(H + (size_t)(r0 + r) * DD + c);
        buf[r * 257 + c + 0] = fmaf(h.x, g_scale[c + 0], g_shift[c + 0]);
        buf[r * 257 + c + 1] = fmaf(h.y, g_scale[c + 1], g_shift[c + 1]);
        buf[r * 257 + c + 2] = fmaf(h.z, g_scale[c + 2], g_shift[c + 2]);
        buf[r * 257 + c + 3] = fmaf(h.w, g_scale[c + 3], g_shift[c + 3]);
    }
    __syncthreads();
    int lane = tid & 31;
    int cbase = tid >> 5;
#pragma unroll
    for (int it = 0; it < 32; it++) {
        int c = cbase + it * 8;
        g_HnT[(size_t)c * NN + r0 + lane] = buf[lane * 257 + c];
    }
}

// ---------------- 4) GEMM: [Hx | G] = Hn @ [W_theta | W_out] + bias ----------------
__global__ __launch_bounds__(256) void k_gemm(
    const float* __restrict__ Wt, const float* __restrict__ bt,
    const float* __restrict__ Wo, const float* __restrict__ bo) {
    __shared__ float As[64 * 64];
    __shared__ float Bs[64 * 64];
    int tid = threadIdx.x, tx = tid & 15, ty = tid >> 4;
    int i0 = blockIdx.x * 64;
    int by = blockIdx.y;
    const float* W    = (by < 4) ? Wt : Wo;
    const float* bias = (by < 4) ? bt : bo;
    float* C          = (by < 4) ? g_Hx : g_G;
    int n0 = (by & 3) * 64;

    float acc[4][4] = {};
    for (int kc = 0; kc < 256; kc += 64) {
#pragma unroll
        for (int it = 0; it < 4; it++) {
            int e = it * 256 + tid;
            int k = e >> 4, r4 = e & 15;
            float4 v = *(const float4*)(g_HnT + (size_t)(kc + k) * NN + i0 + r4 * 4);
            *(float4*)(As + k * 64 + r4 * 4) = v;
        }
#pragma unroll
        for (int it = 0; it < 4; it++) {
            int e = it * 256 + tid;
            int k = e >> 4, n4 = e & 15;
            float4 v = *(const float4*)(W + (size_t)(kc + k) * DD + n0 + n4 * 4);
            *(float4*)(Bs + k * 64 + n4 * 4) = v;
        }
        __syncthreads();
#pragma unroll 8
        for (int k = 0; k < 64; k++) {
            float4 a = *(const float4*)(As + k * 64 + ty * 4);
            float4 b = *(const float4*)(Bs + k * 64 + tx * 4);
            acc[0][0] += a.x * b.x; acc[0][1] += a.x * b.y; acc[0][2] += a.x * b.z; acc[0][3] += a.x * b.w;
            acc[1][0] += a.y * b.x; acc[1][1] += a.y * b.y; acc[1][2] += a.y * b.z; acc[1][3] += a.y * b.w;
            acc[2][0] += a.z * b.x; acc[2][1] += a.z * b.y; acc[2][2] += a.z * b.z; acc[2][3] += a.z * b.w;
            acc[3][0] += a.w * b.x; acc[3][1] += a.w * b.y; acc[3][2] += a.w * b.z; acc[3][3] += a.w * b.w;
        }
        __syncthreads();
    }
#pragma unroll
    for (int q = 0; q < 4; q++) {
        int r = i0 + ty * 4 + q;
#pragma unroll
        for (int p = 0; p < 4; p++) {
            int n = n0 + tx * 4 + p;
            C[(size_t)r * DD + n] = acc[q][p] + bias[n];
        }
    }
}

// ---------------- 5) row-normalize Hx -> F1R (fp32) + F1tf (tf32-rounded) ----------------
__device__ __forceinline__ unsigned f2tf(float x) {
    unsigned r;
    asm("cvt.rna.tf32.f32 %0, %1;" : "=r"(r) : "f"(x));
    return r;
}

__global__ void k_norm() {
    int row = blockIdx.x * 8 + (threadIdx.x >> 5);
    int lane = threadIdx.x & 31;
    const float4* src = (const float4*)(g_Hx + (size_t)row * DD);
    float4 x0 = src[lane];
    float4 x1 = src[lane + 32];
    float s = x0.x * x0.x + x0.y * x0.y + x0.z * x0.z + x0.w * x0.w
            + x1.x * x1.x + x1.y * x1.y + x1.z * x1.z + x1.w * x1.w;
#pragma unroll
    for (int o = 16; o > 0; o >>= 1) s += __shfl_xor_sync(0xffffffffu, s, o);
    float inv = 1.f / fmaxf(sqrtf(s), 1e-12f);
    float4 y0 = make_float4(x0.x * inv, x0.y * inv, x0.z * inv, x0.w * inv);
    float4 y1 = make_float4(x1.x * inv, x1.y * inv, x1.z * inv, x1.w * inv);
    ((float4*)(g_F1R + (size_t)row * DD))[lane]      = y0;
    ((float4*)(g_F1R + (size_t)row * DD))[lane + 32] = y1;
    uint4 t0 = make_uint4(f2tf(y0.x), f2tf(y0.y), f2tf(y0.z), f2tf(y0.w));
    uint4 t1 = make_uint4(f2tf(y1.x), f2tf(y1.y), f2tf(y1.z), f2tf(y1.w));
    ((uint4*)(g_F1tf + (size_t)row * DD))[lane]      = t0;
    ((uint4*)(g_F1tf + (size_t)row * DD))[lane + 32] = t1;
}

// affinity map (fp32, matches reference)
__device__ __forceinline__ float affinity(float d) {
    d = fminf(fmaxf(d, -1.f), 1.f);
    float sam = acosf(d);
    float e = expf(-0.2f * sam);
    float a = 1.f / (1.f + expf(-e));
    return fmaxf(a, 0.1f);
}

__device__ __forceinline__ void mma_tf32(float c[4], const unsigned a[4], const unsigned b[2]) {
    asm volatile(
        "mma.sync.aligned.m16n8k8.row.col.f32.tf32.tf32.f32 "
        "{%0,%1,%2,%3}, {%4,%5,%6,%7}, {%8,%9}, {%0,%1,%2,%3};"
        : "+f"(c[0]), "+f"(c[1]), "+f"(c[2]), "+f"(c[3])
        : "r"(a[0]), "r"(a[1]), "r"(a[2]), "r"(a[3]), "r"(b[0]), "r"(b[1]));
}

// ---------------- 6) main: tf32 tensor-core S fused with approx top-8 + exact rescue ----------------
__global__ __launch_bounds__(256) void k_maintc() {
    extern __shared__ float sm[];
    float* Fi = sm;                      // [64][260] full K panel of this row strip
    float* Fj = sm + RT * FI_PAD;        // [128][68] one k-chunk of j tile
    float* Ss = Fj + JT * FJ_PAD;        // [64][132] staged S tile / merge buffers

    int tid = threadIdx.x;
    int lane = tid & 31, w = tid >> 5;
    int wm = w & 1, wn = w >> 1;         // warp grid 2 (rows) x 4 (cols)
    int gid = lane >> 2, tig = lane & 3;
    int i0 = blockIdx.x * RT;
    int srow = tid >> 2, ssub = tid & 3; // scan: 4 threads per row

    // load Fi (tf32-rounded) full K
#pragma unroll
    for (int it = 0; it < 16; it++) {
        int e = it * 256 + tid;
        int r = e >> 6, k4 = e & 63;
        float4 v = *(const float4*)(g_F1tf + (size_t)(i0 + r) * DD + k4 * 4);
        *(float4*)(Fi + r * FI_PAD + k4 * 4) = v;
    }

    float dv[TOPC]; int dj[TOPC];
#pragma unroll
    for (int m = 0; m < TOPC; m++) { dv[m] = -3.f; dj[m] = 0x7fffffff; }

    __syncthreads();

    for (int jt = 0; jt < NN / JT; jt++) {
        int j0 = jt * JT;
        float acc[2][4][4];
#pragma unroll
        for (int mi = 0; mi < 2; mi++)
#pragma unroll
            for (int ni = 0; ni < 4; ni++)
#pragma unroll
                for (int q = 0; q < 4; q++) acc[mi][ni][q] = 0.f;

        for (int kc = 0; kc < 256; kc += KC) {
            // load Fj chunk: 128 rows x 64 k
#pragma unroll
            for (int it = 0; it < 8; it++) {
                int e = it * 256 + tid;
                int r = e >> 4, k4 = e & 15;
                float4 v = *(const float4*)(g_F1tf + (size_t)(j0 + r) * DD + kc + k4 * 4);
                *(float4*)(Fj + r * FJ_PAD + k4 * 4) = v;
            }
            __syncthreads();
#pragma unroll
            for (int k8 = 0; k8 < KC; k8 += 8) {
                int kA = kc + k8 + tig;
                int kB = k8 + tig;
                unsigned a[2][4], b[4][2];
#pragma unroll
                for (int mi = 0; mi < 2; mi++) {
                    int r = wm * 32 + mi * 16 + gid;
                    a[mi][0] = __float_as_uint(Fi[r * FI_PAD + kA]);
                    a[mi][1] = __float_as_uint(Fi[(r + 8) * FI_PAD + kA]);
                    a[mi][2] = __float_as_uint(Fi[r * FI_PAD + kA + 4]);
                    a[mi][3] = __float_as_uint(Fi[(r + 8) * FI_PAD + kA + 4]);
                }
#pragma unroll
                for (int ni = 0; ni < 4; ni++) {
                    int c = wn * 32 + ni * 8 + gid;
                    b[ni][0] = __float_as_uint(Fj[c * FJ_PAD + kB]);
                    b[ni][1] = __float_as_uint(Fj[c * FJ_PAD + kB + 4]);
                }
#pragma unroll
                for (int mi = 0; mi < 2; mi++)
#pragma unroll
                    for (int ni = 0; ni < 4; ni++)
                        mma_tf32(acc[mi][ni], a[mi], b[ni]);
            }
            __syncthreads();
        }

        // stage S tile
#pragma unroll
        for (int mi = 0; mi < 2; mi++) {
            int r = wm * 32 + mi * 16 + gid;
#pragma unroll
            for (int ni = 0; ni < 4; ni++) {
                int c = wn * 32 + ni * 8 + tig * 2;
                Ss[r * S_PAD + c]           = acc[mi][ni][0];
                Ss[r * S_PAD + c + 1]       = acc[mi][ni][1];
                Ss[(r + 8) * S_PAD + c]     = acc[mi][ni][2];
                Ss[(r + 8) * S_PAD + c + 1] = acc[mi][ni][3];
            }
        }
        __syncthreads();

        // scan: thread owns cols c = 4*i + ssub of row srow (index ascending)
#pragma unroll 8
        for (int i = 0; i < 32; i++) {
            int c = 4 * i + ssub;
            float v = Ss[srow * S_PAD + c];
            int jj = j0 + c;
            if (v > dv[TOPC - 1] || (v == dv[TOPC - 1] && jj < dj[TOPC - 1])) {
                dv[TOPC - 1] = v; dj[TOPC - 1] = jj;
#pragma unroll
                for (int m = TOPC - 1; m > 0; m--) {
                    bool sw = dv[m] > dv[m - 1] || (dv[m] == dv[m - 1] && dj[m] < dj[m - 1]);
                    if (sw) {
                        float tf = dv[m]; dv[m] = dv[m - 1]; dv[m - 1] = tf;
                        int ti = dj[m]; dj[m] = dj[m - 1]; dj[m - 1] = ti;
                    }
                }
            }
        }
        __syncthreads();
    }

    // ---- merge 4 scan-threads per row, then exact fp32 rescue ----
    float* cv = Ss;                 // [64][32] candidate dots
    int*   cj = (int*)(Ss + 64 * 32); // [64][32] candidate indices
#pragma unroll
    for (int m = 0; m < TOPC; m++) {
        cv[srow * 32 + ssub * TOPC + m] = dv[m];
        cj[srow * 32 + ssub * TOPC + m] = dj[m];
    }
    __syncthreads();

    if (tid < RT) {
        int i = i0 + tid;
        float mv[TOPC]; int mj[TOPC];
#pragma unroll
        for (int m = 0; m < TOPC; m++) { mv[m] = -3.f; mj[m] = 0x7fffffff; }
        for (int c = 0; c < 32; c++) {
            float v = cv[tid * 32 + c];
            int jj = cj[tid * 32 + c];
            if (v > mv[TOPC - 1] || (v == mv[TOPC - 1] && jj < mj[TOPC - 1])) {
                mv[TOPC - 1] = v; mj[TOPC - 1] = jj;
#pragma unroll
                for (int m = TOPC - 1; m > 0; m--) {
                    bool sw = mv[m] > mv[m - 1] || (mv[m] == mv[m - 1] && mj[m] < mj[m - 1]);
                    if (sw) {
                        float tf = mv[m]; mv[m] = mv[m - 1]; mv[m - 1] = tf;
                        int ti = mj[m]; mj[m] = mj[m - 1]; mj[m - 1] = ti;
                    }
                }
            }
        }

        // exact fp32 dots, sequential-k chains (same order as the passing R2 kernel)
        float ev[TOPC];
#pragma unroll
        for (int m = 0; m < TOPC; m++) ev[m] = 0.f;
        const float* ri = g_F1R + (size_t)i * DD;
        for (int k = 0; k < DD; k++) {
            float a = ri[k];
#pragma unroll
            for (int m = 0; m < TOPC; m++)
                ev[m] = fmaf(a, g_F1R[(size_t)mj[m] * DD + k], ev[m]);
        }

        // sort candidates by (exact dot desc, idx asc)
#pragma unroll
        for (int m = 1; m < TOPC; m++) {
#pragma unroll
            for (int q = TOPC - 1; q >= 1; q--) {
                bool sw = (ev[q] > ev[q - 1]) ||
                          (ev[q] == ev[q - 1] && mj[q] < mj[q - 1]);
                if (sw) {
                    float tf = ev[q]; ev[q] = ev[q - 1]; ev[q - 1] = tf;
                    int ti = mj[q]; mj[q] = mj[q - 1]; mj[q - 1] = ti;
                }
            }
        }

        // A values + stable sort by (A desc, idx asc) — matches lax.top_k ties
        float av[TOPC];
#pragma unroll
        for (int m = 0; m < TOPC; m++) av[m] = affinity(ev[m]);
#pragma unroll
        for (int m = 1; m < TOPC; m++) {
#pragma unroll
            for (int q = TOPC - 1; q >= 1; q--) {
                bool sw = (av[q] > av[q - 1]) ||
                          (av[q] == av[q - 1] && mj[q] < mj[q - 1]);
                if (sw) {
                    float tf = av[q]; av[q] = av[q - 1]; av[q - 1] = tf;
                    int ti = mj[q]; mj[q] = mj[q - 1]; mj[q - 1] = ti;
                }
            }
        }

        float rs = 0.f;
#pragma unroll
        for (int q = 0; q < TK; q++) {
            rs += av[q];
            g_tv[i * TK + q] = av[q];
            g_ti[i * TK + q] = mj[q];
        }
        g_dinv[i] = rsqrtf(rs);
    }
}

// ---------------- 7) scatter sparse A ----------------
__global__ void k_scatterA(float* __restrict__ A) {
    int e = blockIdx.x * blockDim.x + threadIdx.x;
    if (e < NN * TK) {
        int row = e / TK;
        A[(size_t)row * NN + g_ti[e]] = g_tv[e];
    }
}

// ---------------- 8) out = leaky(A_hat @ G) ----------------
__global__ void k_out(float* __restrict__ out) {
    int i = blockIdx.x;
    int c4 = threadIdx.x;
    float di = g_dinv[i];
    float4 acc = make_float4(0.f, 0.f, 0.f, 0.f);
#pragma unroll
    for (int q = 0; q < TK; q++) {
        int j = g_ti[i * TK + q];
        float w = di * g_tv[i * TK + q] * g_dinv[j];
        float4 g = ((const float4*)(g_G + (size_t)j * DD))[c4];
        acc.x += w * g.x; acc.y += w * g.y; acc.z += w * g.z; acc.w += w * g.w;
    }
    acc.x = acc.x >= 0.f ? acc.x : 0.01f * acc.x;
    acc.y = acc.y >= 0.f ? acc.y : 0.01f * acc.y;
    acc.z = acc.z >= 0.f ? acc.z : 0.01f * acc.z;
    acc.w = acc.w >= 0.f ? acc.w : 0.01f * acc.w;
    ((float4*)(out + (size_t)i * DD))[c4] = acc;
}

// ---------------- launcher ----------------
extern "C" void kernel_launch(void* const* d_in, const int* in_sizes, int n_in,
                              void* d_out, int out_size) {
    const float* H     = (const float*)d_in[0];
    const float* gamma = (const float*)d_in[1];
    const float* beta  = (const float*)d_in[2];
    const float* Wt    = (const float*)d_in[3];
    const float* bt    = (const float*)d_in[4];
    const float* Wo    = (const float*)d_in[5];
    const float* bo    = (const float*)d_in[6];

    float* outbuf = (float*)d_out;
    const long long OUT_ND = (long long)NN * DD;
    const long long A_NN   = (long long)NN * NN;

    float* outp = nullptr;
    float* Ap   = nullptr;
    long long osz = (long long)out_size;
    if (osz == OUT_ND + A_NN)      { outp = outbuf; Ap = outbuf + OUT_ND; }
    else if (osz == A_NN)          { Ap = outbuf; }
    else if (osz == OUT_ND)        { outp = outbuf; }
    else                           { outp = outbuf; if (osz >= OUT_ND + A_NN) Ap = outbuf + OUT_ND; }

    size_t main_smem = (size_t)(RT * FI_PAD + JT * FJ_PAD + RT * S_PAD) * sizeof(float);
    cudaFuncSetAttribute(k_maintc, cudaFuncAttributeMaxDynamicSharedMemorySize, (int)main_smem);

    k_stats1<<<32, 256>>>(H);
    k_stats2<<<1, 256>>>(gamma, beta);
    k_hnT<<<NN / 32, 256>>>(H);
    {
        dim3 g(NN / 64, 8);
        k_gemm<<<g, 256>>>(Wt, bt, Wo, bo);
    }
    k_norm<<<NN / 8, 256>>>();
    k_maintc<<<NN / RT, 256, main_smem>>>();

    if (Ap) {
        cudaMemsetAsync(Ap, 0, (size_t)A_NN * sizeof(float), 0);
        k_scatterA<<<(NN * TK + 255) / 256, 256>>>(Ap);
    }
    if (outp) {
        k_out<<<NN, 64>>>(outp);
    }
}